// round 12
// baseline (speedup 1.0000x reference)
#include <cuda_runtime.h>
#include <cuda_fp16.h>
#include <math.h>
#include <stdint.h>

#define NTOK  131072
#define DIMV  256
#define HID   512
#define NE    16
#define CAP   18023
#define NSLOT (NTOK*2)
#define ECAP  (NE*CAP)
#define NB    32768
#define MTILES ((CAP+127)/128)

// ---------------- scratch (static device globals) ----------------------------
__device__ float g_gate[NSLOT];
__device__ int   g_expert[NSLOT];
__device__ unsigned char g_kept[NSLOT];
__device__ int   g_counts[NE];
__device__ int   g_cursor[NE];
__device__ int   g_perm[ECAP];
__device__ int   g_hist[NE*NB];
__device__ int   g_bstar[NE], g_rrem[NE];
__device__ int   g_blist[NSLOT];
__device__ int   g_btotal;
__device__ float g_imp[NE];
__device__ float g_ent;

__device__ __half g_ctx_h[(size_t)NTOK * DIMV];
__device__ __half g_w1t[(size_t)NE * HID * DIMV];   // [e][h][d]
__device__ __half g_w2t[(size_t)NE * DIMV * HID];   // [e][d][h]
__device__ __half g_y[(size_t)NSLOT * DIMV];

// ---------------- helpers ----------------------------------------------------
__device__ __forceinline__ uint32_t smem_u32(const void* p) {
    uint32_t a;
    asm("{ .reg .u64 t; cvta.to.shared.u64 t, %1; cvt.u32.u64 %0, t; }"
        : "=r"(a) : "l"(p));
    return a;
}
__device__ __forceinline__ void cpasync16(uint32_t dst, const void* src, int srcsz) {
    asm volatile("cp.async.cg.shared.global [%0], [%1], 16, %2;"
                 :: "r"(dst), "l"(src), "r"(srcsz) : "memory");
}
#define CP_COMMIT() asm volatile("cp.async.commit_group;" ::: "memory")
#define CP_WAIT2()  asm volatile("cp.async.wait_group 2;" ::: "memory")
#define CP_WAIT1()  asm volatile("cp.async.wait_group 1;" ::: "memory")
#define CP_WAIT0()  asm volatile("cp.async.wait_group 0;" ::: "memory")

__device__ __forceinline__ void ldsm4(uint32_t* r, uint32_t addr) {
    asm volatile("ldmatrix.sync.aligned.m8n8.x4.shared.b16 {%0,%1,%2,%3}, [%4];"
                 : "=r"(r[0]), "=r"(r[1]), "=r"(r[2]), "=r"(r[3]) : "r"(addr));
}
__device__ __forceinline__ void sts32(uint32_t addr, uint32_t v) {
    asm volatile("st.shared.b32 [%0], %1;" :: "r"(addr), "r"(v) : "memory");
}
__device__ __forceinline__ void mma16816(float* c, const uint32_t* a, const uint32_t* b) {
    asm volatile(
        "mma.sync.aligned.m16n8k16.row.col.f32.f16.f16.f32 "
        "{%0,%1,%2,%3}, {%4,%5,%6,%7}, {%8,%9}, {%0,%1,%2,%3};"
        : "+f"(c[0]), "+f"(c[1]), "+f"(c[2]), "+f"(c[3])
        : "r"(a[0]), "r"(a[1]), "r"(a[2]), "r"(a[3]), "r"(b[0]), "r"(b[1]));
}
__device__ __forceinline__ uint32_t packh(__half a, __half b) {
    return (uint32_t)__half_as_ushort(a) | ((uint32_t)__half_as_ushort(b) << 16);
}

// ---------- fused-MLP smem: compact 64B rows, XOR swizzle seg^=(row>>1)&3 ----
#define FS_SLOT 0
#define FS_GATE 512
#define FS_X    1024
#define FS_W1   (FS_X  + 65536)
#define FS_W2   (FS_W1 + 65536)
#define FS_H    (FS_W2 + 65536)
#define FS_SZ   (FS_H  + 32768)        // 230400

// ---------------- zero -------------------------------------------------------
__global__ void k_zero() {
    int i = blockIdx.x * blockDim.x + threadIdx.x;
    for (int j = i; j < NE*NB; j += gridDim.x * blockDim.x) g_hist[j] = 0;
    if (i < NE) { g_counts[i] = 0; g_cursor[i] = 0; g_imp[i] = 0.f; }
    if (i == 0) { g_ent = 0.f; g_btotal = 0; }
}

// ---------------- coalesced transpose + fp16 convert -------------------------
__global__ void k_transpose(const float* __restrict__ src, int which, int R, int C) {
    __shared__ float tile[32][33];
    __half* dstg = which ? g_w2t : g_w1t;
    int e = blockIdx.z;
    const float* S = src + (size_t)e * R * C;
    __half* D = dstg + (size_t)e * R * C;
    int c0 = blockIdx.x * 32, r0 = blockIdx.y * 32;
    int tc = threadIdx.x & 31, tr4 = threadIdx.x >> 5;
#pragma unroll
    for (int i = 0; i < 4; i++) {
        int r = tr4 + i*8;
        tile[r][tc] = S[(size_t)(r0 + r)*C + c0 + tc];
    }
    __syncthreads();
#pragma unroll
    for (int i = 0; i < 4; i++) {
        int r = tr4 + i*8;
        D[(size_t)(c0 + r)*R + r0 + tc] = __float2half_rn(tile[tc][r]);
    }
}

// ---------------- router: 4 threads/token, 8 tokens/warp, high-occ ----------
__global__ void __launch_bounds__(256, 7)
k_router(const float* __restrict__ ctx,
         const float* __restrict__ Wg,
         const float* __restrict__ bg) {
    __shared__ float sWT[DIMV*20];
    __shared__ float s_imp[NE];
    __shared__ float s_ent;
    __shared__ float s_bg[NE];
    int tid = threadIdx.x;
    for (int i = tid; i < NE*DIMV; i += blockDim.x)
        sWT[(i >> 4)*20 + (i & 15)] = Wg[i];
    if (tid < NE) { s_imp[tid] = 0.f; s_bg[tid] = bg[tid]; }
    if (tid == 0) s_ent = 0.f;
    __syncthreads();

    int warp = tid >> 5, lane = tid & 31;
    int q = lane & 3;
    int t = blockIdx.x * 64 + warp * 8 + (lane >> 2);
    const float* x = ctx + (size_t)t * DIMV;

    float acc[NE];
#pragma unroll
    for (int e = 0; e < NE; e++) acc[e] = 0.f;
#pragma unroll 16
    for (int i = 0; i < 64; i++) {
        int d = i*4 + q;
        float xv = x[d];
        const float4* wrow = (const float4*)&sWT[d*20];
#pragma unroll
        for (int e4 = 0; e4 < 4; e4++) {
            float4 w = wrow[e4];
            acc[e4*4+0] += xv * w.x;
            acc[e4*4+1] += xv * w.y;
            acc[e4*4+2] += xv * w.z;
            acc[e4*4+3] += xv * w.w;
        }
    }
#pragma unroll
    for (int e = 0; e < NE; e++) {
        acc[e] += __shfl_xor_sync(0xffffffffu, acc[e], 1);
        acc[e] += __shfl_xor_sync(0xffffffffu, acc[e], 2);
        acc[e] += s_bg[e];
    }

    int i0 = 0; float v0 = acc[0];
#pragma unroll
    for (int e = 1; e < NE; e++) if (acc[e] > v0) { v0 = acc[e]; i0 = e; }
    int i1 = (i0 == 0) ? 1 : 0; float v1 = acc[i1];
#pragma unroll
    for (int e = 0; e < NE; e++)
        if (e != i0 && acc[e] > v1) { v1 = acc[e]; i1 = e; }

    float sum = 0.f;
#pragma unroll
    for (int e = 0; e < NE; e++) { acc[e] = __expf(acc[e] - v0); sum += acc[e]; }
    float inv = 1.f / sum;
    float ent = 0.f;
#pragma unroll
    for (int e = 0; e < NE; e++) {
        acc[e] *= inv;
        ent -= acc[e] * __logf(fmaxf(acc[e], 1e-9f));
    }
#pragma unroll
    for (int e = 0; e < NE; e++) {
        acc[e] += __shfl_xor_sync(0xffffffffu, acc[e], 4);
        acc[e] += __shfl_xor_sync(0xffffffffu, acc[e], 8);
        acc[e] += __shfl_xor_sync(0xffffffffu, acc[e], 16);
    }
    ent += __shfl_xor_sync(0xffffffffu, ent, 4);
    ent += __shfl_xor_sync(0xffffffffu, ent, 8);
    ent += __shfl_xor_sync(0xffffffffu, ent, 16);
    if (lane == 0) {
#pragma unroll
        for (int e = 0; e < NE; e++) atomicAdd(&s_imp[e], acc[e]);
        atomicAdd(&s_ent, ent);
    }

    if (q == 0) {
        float ex = __expf(v1 - v0);
        float gg0 = 1.f / (1.f + ex);
        float gg1 = ex / (1.f + ex);
        int s0 = 2*t, s1 = 2*t + 1;
        g_expert[s0] = i0; g_expert[s1] = i1;
        g_gate[s0] = gg0;  g_gate[s1] = gg1;
        atomicAdd(&g_counts[i0], 1);
        atomicAdd(&g_counts[i1], 1);
        atomicAdd(&g_hist[i0*NB + (int)(__float_as_uint(gg0) >> 17)], 1);
        atomicAdd(&g_hist[i1*NB + (int)(__float_as_uint(gg1) >> 17)], 1);
    }
    __syncthreads();
    if (tid < NE) atomicAdd(&g_imp[tid], s_imp[tid]);
    if (tid == 0) atomicAdd(&g_ent, s_ent);

    {
        const float4* src = (const float4*)(ctx + (size_t)blockIdx.x * 64 * DIMV);
        uint2* dst = (uint2*)(g_ctx_h + (size_t)blockIdx.x * 64 * DIMV);
#pragma unroll
        for (int i = 0; i < 16; i++) {
            int j = tid + i*256;
            float4 v = src[j];
            uint2 pk;
            pk.x = packh(__float2half_rn(v.x), __float2half_rn(v.y));
            pk.y = packh(__float2half_rn(v.z), __float2half_rn(v.w));
            dst[j] = pk;
        }
    }
}

// ---------------- capacity cutoff --------------------------------------------
__global__ void k_cutoff() {
    int e = blockIdx.x, tid = threadIdx.x;
    __shared__ int chunk[256], suffix[256];
    if (g_counts[e] <= CAP) {
        if (tid == 0) { g_bstar[e] = -1; g_rrem[e] = 0; }
        return;
    }
    const int* h = g_hist + e*NB;
    int b0 = tid * 128;
    int s = 0;
    for (int b = b0; b < b0 + 128; b++) s += h[b];
    chunk[tid] = s;
    __syncthreads();
    if (tid == 0) {
        int run = 0;
        for (int i = 255; i >= 0; i--) { suffix[i] = run; run += chunk[i]; }
    }
    __syncthreads();
    int cum = suffix[tid];
    for (int b = b0 + 127; b >= b0; b--) {
        int hb = h[b];
        if (cum < CAP && cum + hb >= CAP) {
            g_bstar[e] = b; g_rrem[e] = CAP - cum;
        }
        cum += hb;
    }
}

__global__ void k_flags() {
    int s = blockIdx.x * blockDim.x + threadIdx.x;
    if (s >= NSLOT) return;
    int e = g_expert[s];
    unsigned char kept;
    if (g_counts[e] <= CAP) kept = 1;
    else {
        int b  = (int)(__float_as_uint(g_gate[s]) >> 17);
        int bs = g_bstar[e];
        if (b > bs) kept = 1;
        else if (b < bs) kept = 0;
        else {
            kept = 0;
            int p = atomicAdd(&g_btotal, 1);
            g_blist[p] = s;
        }
    }
    g_kept[s] = kept;
}

__global__ void k_boundary() {
    int total = g_btotal;
    for (int i = blockIdx.x * blockDim.x + threadIdx.x; i < total;
         i += gridDim.x * blockDim.x) {
        int si = g_blist[i];
        int e  = g_expert[si];
        unsigned int ki = __float_as_uint(g_gate[si]);
        int better = 0;
        for (int j = 0; j < total; j++) {
            int sj = g_blist[j];
            if (g_expert[sj] != e) continue;
            unsigned int kj = __float_as_uint(g_gate[sj]);
            better += (kj > ki) || (kj == ki && sj < si);
        }
        if (better < g_rrem[e]) g_kept[si] = 1;
    }
}

__global__ void k_compact() {
    __shared__ int scnt[NE], sbase[NE];
    int tid = threadIdx.x;
    int s = blockIdx.x * 256 + tid;
    if (tid < NE) scnt[tid] = 0;
    __syncthreads();
    int e = -1, rank = 0;
    if (s < NSLOT && g_kept[s]) {
        e = g_expert[s];
        rank = atomicAdd(&scnt[e], 1);
    }
    __syncthreads();
    if (tid < NE && scnt[tid] > 0) sbase[tid] = atomicAdd(&g_cursor[tid], scnt[tid]);
    __syncthreads();
    if (e >= 0) g_perm[e*CAP + sbase[e] + rank] = s;
}

// ---------------- fused MLP, pipelined ---------------------------------------
__global__ void __launch_bounds__(256, 1)
k_mlp(const float* __restrict__ b1, const float* __restrict__ b2) {
    int e = blockIdx.z;
    int Me = min(g_counts[e], CAP);
    int m0 = blockIdx.x * 128;
    if (m0 >= Me) return;

    extern __shared__ __align__(16) char smem[];
    uint32_t sb = smem_u32(smem);
    int tid = threadIdx.x;
    int* sslot = (int*)smem;
    float* sgate = (float*)(smem + FS_GATE);
    if (tid < 128) {
        int gr = m0 + tid;
        if (gr < Me) {
            int s = g_perm[e*CAP + gr];
            sslot[tid] = s; sgate[tid] = g_gate[s];
        } else { sslot[tid] = -1; sgate[tid] = 0.f; }
    }
    __syncthreads();

    const __half* W1 = g_w1t + (size_t)e * HID * DIMV;
    const __half* W2 = g_w2t + (size_t)e * DIMV * HID;

#pragma unroll
    for (int i = 0; i < 16; i++) {
        int j = tid + i*256;
        int c = j >> 9, rem = j & 511;
        int row = rem >> 2, seg = rem & 3;
        int tok = sslot[row] >> 1;
        cpasync16(sb + FS_X + c*8192 + row*64 + ((seg ^ ((row>>1)&3))*16),
                  g_ctx_h + (size_t)max(tok, 0)*DIMV + c*32 + seg*8,
                  tok >= 0 ? 16 : 0);
    }
    CP_COMMIT();

    auto fill_w1 = [&](int st, int h0) {
#pragma unroll
        for (int i = 0; i < 8; i++) {
            int j = tid + i*256;
            int c = j >> 8, rem = j & 255;
            int r = rem >> 2, seg = rem & 3;
            cpasync16(sb + FS_W1 + st*32768 + c*4096 + r*64 + ((seg ^ ((r>>1)&3))*16),
                      W1 + (size_t)(h0 + r)*DIMV + c*32 + seg*8, 16);
        }
        CP_COMMIT();
    };
    auto fill_w2 = [&](int st, int h0) {
#pragma unroll
        for (int i = 0; i < 8; i++) {
            int j = tid + i*256;
            int kc = j >> 10, rem = j & 1023;
            int r = rem >> 2, seg = rem & 3;
            cpasync16(sb + FS_W2 + st*32768 + kc*16384 + r*64 + ((seg ^ ((r>>1)&3))*16),
                      W2 + (size_t)r*HID + h0 + kc*32 + seg*8, 16);
        }
        CP_COMMIT();
    };

    fill_w1(0, 0);
    fill_w2(0, 0);
    fill_w1(1, 64);

    int warp = tid >> 5, lane = tid & 31;
    int g = lane >> 2, tg = lane & 3;
    int wmP = (warp & 3) * 32, wnP = (warp >> 2) * 32;
    int wm = (warp & 1) * 64, wn = (warp >> 1) * 64;

    int lrA = lane & 15;
    int lrB = ((lane >> 4) & 1)*8 + (lane & 7);
    uint32_t x0 = (lane >> 1) & 1, x1 = (lane >> 2) & 1;
    uint32_t aSwz = ((((lane >> 4) & 1) ^ x0)) * 16;
    uint32_t bSwz = ((((lane >> 3) & 1) ^ x0)) * 16;
    uint32_t sx   = x1 * 32;
    uint32_t aP0 = (uint32_t)(wmP + lrA)*64 + aSwz;
    uint32_t bP0 = (uint32_t)(wnP + lrB)*64 + bSwz;
    uint32_t aO0 = (uint32_t)(wm + lrA)*64 + aSwz;
    uint32_t bO0 = (uint32_t)(wn + lrB)*64 + bSwz;
    uint32_t hsw = (uint32_t)((g >> 1) & 3);

    float accO[4][8][4];
#pragma unroll
    for (int a = 0; a < 4; a++)
#pragma unroll
        for (int b = 0; b < 8; b++)
#pragma unroll
            for (int cc = 0; cc < 4; cc++) accO[a][b][cc] = 0.f;

    const float* bias1 = b1 + (size_t)e * HID;

    CP_WAIT2();
    __syncthreads();
    {
        float accP[2][4][4];
#pragma unroll
        for (int a = 0; a < 2; a++)
#pragma unroll
            for (int b = 0; b < 4; b++)
#pragma unroll
                for (int cc = 0; cc < 4; cc++) accP[a][b][cc] = 0.f;
        uint32_t w1b = sb + FS_W1;
#pragma unroll
        for (int c = 0; c < 8; c++) {
#pragma unroll
            for (int s = 0; s < 2; s++) {
                uint32_t sterm = ((uint32_t)(s*32)) ^ sx;
                uint32_t Af[2][4], Bf[4][2];
#pragma unroll
                for (int mf = 0; mf < 2; mf++)
                    ldsm4(Af[mf], sb + FS_X + c*8192 + aP0 + mf*(16*64) + sterm);
#pragma unroll
                for (int p = 0; p < 2; p++)
                    ldsm4(&Bf[2*p][0], w1b + c*4096 + bP0 + p*(16*64) + sterm);
#pragma unroll
                for (int mf = 0; mf < 2; mf++)
#pragma unroll
                    for (int nf = 0; nf < 4; nf++)
                        mma16816(accP[mf][nf], Af[mf], Bf[nf]);
            }
        }
#pragma unroll
        for (int nf = 0; nf < 4; nf++) {
            int cl = wnP + nf*8 + tg*2;
            float2 bb = *(const float2*)(bias1 + cl);
            int kc = cl >> 5, colb = (cl & 31)*2;
            uint32_t coff = (uint32_t)kc*8192 +
                            (uint32_t)(((uint32_t)(colb >> 4) ^ hsw))*16 + (colb & 15);
#pragma unroll
            for (int mf = 0; mf < 2; mf++)
#pragma unroll
                for (int hv = 0; hv < 2; hv++) {
                    int row = wmP + mf*16 + g + hv*8;
                    float v0 = fmaxf(accP[mf][nf][hv*2+0] + bb.x, 0.f);
                    float v1 = fmaxf(accP[mf][nf][hv*2+1] + bb.y, 0.f);
                    sts32(sb + FS_H + coff + (uint32_t)row*64,
                          packh(__float2half_rn(v0), __float2half_rn(v1)));
                }
        }
    }

    for (int h = 0; h < 8; h++) {
        __syncthreads();
        if (h < 7) fill_w2((h + 1) & 1, (h + 1) * 64);
        if (h < 6) fill_w1(h & 1, (h + 2) * 64);
        if (h < 6) CP_WAIT2();
        else if (h == 6) CP_WAIT1();
        else CP_WAIT0();
        __syncthreads();

        if (h < 7) {
            int hp = h + 1;
            float accP[2][4][4];
#pragma unroll
            for (int a = 0; a < 2; a++)
#pragma unroll
                for (int b = 0; b < 4; b++)
#pragma unroll
                    for (int cc = 0; cc < 4; cc++) accP[a][b][cc] = 0.f;
            uint32_t w1b = sb + FS_W1 + (hp & 1)*32768;
#pragma unroll
            for (int c = 0; c < 8; c++) {
#pragma unroll
                for (int s = 0; s < 2; s++) {
                    uint32_t sterm = ((uint32_t)(s*32)) ^ sx;
                    uint32_t Af[2][4], Bf[4][2];
#pragma unroll
                    for (int mf = 0; mf < 2; mf++)
                        ldsm4(Af[mf], sb + FS_X + c*8192 + aP0 + mf*(16*64) + sterm);
#pragma unroll
                    for (int p = 0; p < 2; p++)
                        ldsm4(&Bf[2*p][0], w1b + c*4096 + bP0 + p*(16*64) + sterm);
#pragma unroll
                    for (int mf = 0; mf < 2; mf++)
#pragma unroll
                        for (int nf = 0; nf < 4; nf++)
                            mma16816(accP[mf][nf], Af[mf], Bf[nf]);
                }
            }
            uint32_t hdst = sb + FS_H + (hp & 1)*16384;
#pragma unroll
            for (int nf = 0; nf < 4; nf++) {
                int cl = wnP + nf*8 + tg*2;
                float2 bb = *(const float2*)(bias1 + hp*64 + cl);
                int kc = cl >> 5, colb = (cl & 31)*2;
                uint32_t coff = (uint32_t)kc*8192 +
                                (uint32_t)(((uint32_t)(colb >> 4) ^ hsw))*16 + (colb & 15);
#pragma unroll
                for (int mf = 0; mf < 2; mf++)
#pragma unroll
                    for (int hv = 0; hv < 2; hv++) {
                        int row = wmP + mf*16 + g + hv*8;
                        float v0 = fmaxf(accP[mf][nf][hv*2+0] + bb.x, 0.f);
                        float v1 = fmaxf(accP[mf][nf][hv*2+1] + bb.y, 0.f);
                        sts32(hdst + coff + (uint32_t)row*64,
                              packh(__float2half_rn(v0), __float2half_rn(v1)));
                    }
            }
        }

        uint32_t hb  = sb + FS_H  + (h & 1)*16384;
        uint32_t w2b = sb + FS_W2 + (h & 1)*32768;
#pragma unroll
        for (int kc = 0; kc < 2; kc++) {
#pragma unroll
            for (int s = 0; s < 2; s++) {
                uint32_t sterm = ((uint32_t)(s*32)) ^ sx;
                uint32_t Af[4][4], Bf[8][2];
#pragma unroll
                for (int mf = 0; mf < 4; mf++)
                    ldsm4(Af[mf], hb + kc*8192 + aO0 + mf*(16*64) + sterm);
#pragma unroll
                for (int p = 0; p < 4; p++)
                    ldsm4(&Bf[2*p][0], w2b + kc*16384 + bO0 + p*(16*64) + sterm);
#pragma unroll
                for (int mf = 0; mf < 4; mf++)
#pragma unroll
                    for (int nf = 0; nf < 8; nf++)
                        mma16816(accO[mf][nf], Af[mf], Bf[nf]);
            }
        }
    }

    const float* bias2 = b2 + (size_t)e * DIMV;
#pragma unroll
    for (int mf = 0; mf < 4; mf++) {
#pragma unroll
        for (int hv = 0; hv < 2; hv++) {
            int r = wm + mf*16 + g + hv*8;
            int slot = sslot[r];
            if (slot < 0) continue;
            float gate = sgate[r];
            __half* yr = g_y + (size_t)slot * DIMV;
#pragma unroll
            for (int nf = 0; nf < 8; nf++) {
                int col = wn + nf*8 + tg*2;
                float2 bb = *(const float2*)(bias2 + col);
                float v0 = (accO[mf][nf][hv*2+0] + bb.x) * gate;
                float v1 = (accO[mf][nf][hv*2+1] + bb.y) * gate;
                *(uint32_t*)(yr + col) = packh(__float2half_rn(v0), __float2half_rn(v1));
            }
        }
    }
}

// ---------------- combine (fp16 y) + fused finalize ---------------------------
__global__ void k_combine(float* __restrict__ out, int out_size) {
    int idx = blockIdx.x * blockDim.x + threadIdx.x;
    if (idx < NTOK * 32) {
        int t = idx >> 5, f = idx & 31;
        float r[8];
#pragma unroll
        for (int i = 0; i < 8; i++) r[i] = 0.f;
        if (g_kept[2*t]) {
            uint4 a = *(const uint4*)(g_y + (size_t)(2*t)*DIMV + f*8);
            const uint32_t* w = (const uint32_t*)&a;
#pragma unroll
            for (int i = 0; i < 4; i++) {
                __half2 h2 = *(const __half2*)&w[i];
                float2 v = __half22float2(h2);
                r[2*i] += v.x; r[2*i+1] += v.y;
            }
        }
        if (g_kept[2*t + 1]) {
            uint4 a = *(const uint4*)(g_y + (size_t)(2*t+1)*DIMV + f*8);
            const uint32_t* w = (const uint32_t*)&a;
#pragma unroll
            for (int i = 0; i < 4; i++) {
                __half2 h2 = *(const __half2*)&w[i];
                float2 v = __half22float2(h2);
                r[2*i] += v.x; r[2*i+1] += v.y;
            }
        }
        float* o = out + (size_t)t*DIMV + f*8;
        *(float4*)o     = make_float4(r[0], r[1], r[2], r[3]);
        *(float4*)(o+4) = make_float4(r[4], r[5], r[6], r[7]);
    }
    // fused finalize: block 0, first warp (inputs ready before this launch)
    if (blockIdx.x == 0 && threadIdx.x < 32) {
        int lane = threadIdx.x;
        int c = (lane < NE) ? min(g_counts[lane], CAP) : 0;
        int tot = c;
#pragma unroll
        for (int off = 16; off; off >>= 1) tot += __shfl_xor_sync(0xffffffffu, tot, off);
        float denom = fmaxf((float)tot, 1.f);
        float aux = 0.f;
        if (lane < NE)
            aux = (g_imp[lane] / (float)NTOK) * ((float)c / denom) * (float)NE;
#pragma unroll
        for (int off = 16; off; off >>= 1) aux += __shfl_xor_sync(0xffffffffu, aux, off);
        int base = NTOK * DIMV;
        if (lane == 0 && out_size > base)     out[base]     = aux;
        if (lane == 0 && out_size > base + 1) out[base + 1] = g_ent / (float)NTOK;
        if (lane < NE && out_size > base + 2 + lane) out[base + 2 + lane] = (float)c;
    }
}

// ---------------- launch -----------------------------------------------------
extern "C" void kernel_launch(void* const* d_in, const int* in_sizes, int n_in,
                              void* d_out, int out_size) {
    const float* ctx = (const float*)d_in[0];
    const float* Wg  = (const float*)d_in[1];
    const float* bg  = (const float*)d_in[2];
    const float* W1  = (const float*)d_in[3];
    const float* b1  = (const float*)d_in[4];
    const float* W2  = (const float*)d_in[5];
    const float* b2  = (const float*)d_in[6];
    float* out = (float*)d_out;

    static cudaStream_t s1;
    static cudaEvent_t evFork, evJoin;
    static bool init_done = false;
    if (!init_done) {
        cudaFuncSetAttribute(k_mlp, cudaFuncAttributeMaxDynamicSharedMemorySize, FS_SZ);
        cudaStreamCreateWithFlags(&s1, cudaStreamNonBlocking);
        cudaEventCreateWithFlags(&evFork, cudaEventDisableTiming);
        cudaEventCreateWithFlags(&evJoin, cudaEventDisableTiming);
        init_done = true;
    }

    // main: zero (router depends on it)
    k_zero<<<512, 256>>>();

    // fork: weight transposes run concurrently with router + dispatch chain
    cudaEventRecord(evFork, 0);
    cudaStreamWaitEvent(s1, evFork, 0);
    k_transpose<<<dim3(HID/32, DIMV/32, NE), 256, 0, s1>>>(W1, 0, DIMV, HID);
    k_transpose<<<dim3(DIMV/32, HID/32, NE), 256, 0, s1>>>(W2, 1, HID, DIMV);
    cudaEventRecord(evJoin, s1);

    // main: router + dispatch
    k_router<<<NTOK/64, 256>>>(ctx, Wg, bg);
    k_cutoff<<<NE, 256>>>();
    k_flags<<<NSLOT/256, 256>>>();
    k_boundary<<<64, 256>>>();
    k_compact<<<(NSLOT + 255)/256, 256>>>();

    // join before MLP (needs transposed weights)
    cudaStreamWaitEvent(0, evJoin, 0);

    dim3 gm(MTILES, 1, NE);
    k_mlp<<<gm, 256, FS_SZ>>>(b1, b2);

    k_combine<<<(NTOK*32 + 255)/256, 256>>>(out, out_size);
}

// round 13
// speedup vs baseline: 1.0400x; 1.0400x over previous
#include <cuda_runtime.h>
#include <cuda_fp16.h>
#include <math.h>
#include <stdint.h>

#define NTOK  131072
#define DIMV  256
#define HID   512
#define NE    16
#define CAP   18023
#define NSLOT (NTOK*2)
#define ECAP  (NE*CAP)
#define NB    32768
#define MTILES ((CAP+127)/128)

// ---------------- scratch (static device globals) ----------------------------
__device__ float g_gate[NSLOT];
__device__ int   g_expert[NSLOT];
__device__ unsigned char g_kept[NSLOT];
__device__ int   g_counts[NE];
__device__ int   g_cursor[NE];
__device__ int   g_perm[ECAP];
__device__ int   g_hist[NE*NB];
__device__ int   g_bstar[NE], g_rrem[NE];
__device__ int   g_blist[NSLOT];
__device__ int   g_btotal;
__device__ float g_imp[NE];
__device__ float g_ent;

__device__ __half g_ctx_h[(size_t)NTOK * DIMV];
__device__ __half g_w1t[(size_t)NE * HID * DIMV];   // [e][h][d]
__device__ __half g_w2t[(size_t)NE * DIMV * HID];   // [e][d][h]
__device__ __half g_y[(size_t)NSLOT * DIMV];

// ---------------- helpers ----------------------------------------------------
__device__ __forceinline__ uint32_t smem_u32(const void* p) {
    uint32_t a;
    asm("{ .reg .u64 t; cvta.to.shared.u64 t, %1; cvt.u32.u64 %0, t; }"
        : "=r"(a) : "l"(p));
    return a;
}
__device__ __forceinline__ void cpasync16(uint32_t dst, const void* src, int srcsz) {
    asm volatile("cp.async.cg.shared.global [%0], [%1], 16, %2;"
                 :: "r"(dst), "l"(src), "r"(srcsz) : "memory");
}
#define CP_COMMIT() asm volatile("cp.async.commit_group;" ::: "memory")
#define CP_WAIT2()  asm volatile("cp.async.wait_group 2;" ::: "memory")
#define CP_WAIT1()  asm volatile("cp.async.wait_group 1;" ::: "memory")
#define CP_WAIT0()  asm volatile("cp.async.wait_group 0;" ::: "memory")

__device__ __forceinline__ void ldsm4(uint32_t* r, uint32_t addr) {
    asm volatile("ldmatrix.sync.aligned.m8n8.x4.shared.b16 {%0,%1,%2,%3}, [%4];"
                 : "=r"(r[0]), "=r"(r[1]), "=r"(r[2]), "=r"(r[3]) : "r"(addr));
}
__device__ __forceinline__ void sts32(uint32_t addr, uint32_t v) {
    asm volatile("st.shared.b32 [%0], %1;" :: "r"(addr), "r"(v) : "memory");
}
__device__ __forceinline__ void mma16816(float* c, const uint32_t* a, const uint32_t* b) {
    asm volatile(
        "mma.sync.aligned.m16n8k16.row.col.f32.f16.f16.f32 "
        "{%0,%1,%2,%3}, {%4,%5,%6,%7}, {%8,%9}, {%0,%1,%2,%3};"
        : "+f"(c[0]), "+f"(c[1]), "+f"(c[2]), "+f"(c[3])
        : "r"(a[0]), "r"(a[1]), "r"(a[2]), "r"(a[3]), "r"(b[0]), "r"(b[1]));
}
__device__ __forceinline__ uint32_t packh(__half a, __half b) {
    return (uint32_t)__half_as_ushort(a) | ((uint32_t)__half_as_ushort(b) << 16);
}

// ---------- fused-MLP smem: compact 64B rows, XOR swizzle seg^=(row>>1)&3 ----
#define FS_SLOT 0
#define FS_GATE 512
#define FS_X    1024
#define FS_W1   (FS_X  + 65536)
#define FS_W2   (FS_W1 + 65536)
#define FS_H    (FS_W2 + 65536)
#define FS_SZ   (FS_H  + 32768)        // 230400

// ---------------- zero -------------------------------------------------------
__global__ void k_zero() {
    int i = blockIdx.x * blockDim.x + threadIdx.x;
    for (int j = i; j < NE*NB; j += gridDim.x * blockDim.x) g_hist[j] = 0;
    if (i < NE) { g_counts[i] = 0; g_cursor[i] = 0; g_imp[i] = 0.f; }
    if (i == 0) { g_ent = 0.f; g_btotal = 0; }
}

// ---------------- coalesced transpose + fp16 convert -------------------------
__global__ void k_transpose(const float* __restrict__ src, int which, int R, int C) {
    __shared__ float tile[32][33];
    __half* dstg = which ? g_w2t : g_w1t;
    int e = blockIdx.z;
    const float* S = src + (size_t)e * R * C;
    __half* D = dstg + (size_t)e * R * C;
    int c0 = blockIdx.x * 32, r0 = blockIdx.y * 32;
    int tc = threadIdx.x & 31, tr4 = threadIdx.x >> 5;
#pragma unroll
    for (int i = 0; i < 4; i++) {
        int r = tr4 + i*8;
        tile[r][tc] = S[(size_t)(r0 + r)*C + c0 + tc];
    }
    __syncthreads();
#pragma unroll
    for (int i = 0; i < 4; i++) {
        int r = tr4 + i*8;
        D[(size_t)(c0 + r)*R + r0 + tc] = __float2half_rn(tile[tc][r]);
    }
}

// ---------------- router: 4 threads/token, 8 tokens/warp --------------------
__global__ void k_router(const float* __restrict__ ctx,
                         const float* __restrict__ Wg,
                         const float* __restrict__ bg) {
    __shared__ float sWT[DIMV*20];
    __shared__ float s_imp[NE];
    __shared__ float s_ent;
    __shared__ float s_bg[NE];
    int tid = threadIdx.x;
    for (int i = tid; i < NE*DIMV; i += blockDim.x)
        sWT[(i >> 4)*20 + (i & 15)] = Wg[i];
    if (tid < NE) { s_imp[tid] = 0.f; s_bg[tid] = bg[tid]; }
    if (tid == 0) s_ent = 0.f;
    __syncthreads();

    int warp = tid >> 5, lane = tid & 31;
    int q = lane & 3;
    int t = blockIdx.x * 64 + warp * 8 + (lane >> 2);
    const float* x = ctx + (size_t)t * DIMV;

    float acc[NE];
#pragma unroll
    for (int e = 0; e < NE; e++) acc[e] = 0.f;
#pragma unroll 16
    for (int i = 0; i < 64; i++) {
        int d = i*4 + q;
        float xv = x[d];
        const float4* wrow = (const float4*)&sWT[d*20];
#pragma unroll
        for (int e4 = 0; e4 < 4; e4++) {
            float4 w = wrow[e4];
            acc[e4*4+0] += xv * w.x;
            acc[e4*4+1] += xv * w.y;
            acc[e4*4+2] += xv * w.z;
            acc[e4*4+3] += xv * w.w;
        }
    }
#pragma unroll
    for (int e = 0; e < NE; e++) {
        acc[e] += __shfl_xor_sync(0xffffffffu, acc[e], 1);
        acc[e] += __shfl_xor_sync(0xffffffffu, acc[e], 2);
        acc[e] += s_bg[e];
    }

    int i0 = 0; float v0 = acc[0];
#pragma unroll
    for (int e = 1; e < NE; e++) if (acc[e] > v0) { v0 = acc[e]; i0 = e; }
    int i1 = (i0 == 0) ? 1 : 0; float v1 = acc[i1];
#pragma unroll
    for (int e = 0; e < NE; e++)
        if (e != i0 && acc[e] > v1) { v1 = acc[e]; i1 = e; }

    float sum = 0.f;
#pragma unroll
    for (int e = 0; e < NE; e++) { acc[e] = __expf(acc[e] - v0); sum += acc[e]; }
    float inv = 1.f / sum;
    float ent = 0.f;
#pragma unroll
    for (int e = 0; e < NE; e++) {
        acc[e] *= inv;
        ent -= acc[e] * __logf(fmaxf(acc[e], 1e-9f));
    }
#pragma unroll
    for (int e = 0; e < NE; e++) {
        acc[e] += __shfl_xor_sync(0xffffffffu, acc[e], 4);
        acc[e] += __shfl_xor_sync(0xffffffffu, acc[e], 8);
        acc[e] += __shfl_xor_sync(0xffffffffu, acc[e], 16);
    }
    ent += __shfl_xor_sync(0xffffffffu, ent, 4);
    ent += __shfl_xor_sync(0xffffffffu, ent, 8);
    ent += __shfl_xor_sync(0xffffffffu, ent, 16);
    if (lane == 0) {
#pragma unroll
        for (int e = 0; e < NE; e++) atomicAdd(&s_imp[e], acc[e]);
        atomicAdd(&s_ent, ent);
    }

    if (q == 0) {
        float ex = __expf(v1 - v0);
        float gg0 = 1.f / (1.f + ex);
        float gg1 = ex / (1.f + ex);
        int s0 = 2*t, s1 = 2*t + 1;
        g_expert[s0] = i0; g_expert[s1] = i1;
        g_gate[s0] = gg0;  g_gate[s1] = gg1;
        atomicAdd(&g_counts[i0], 1);
        atomicAdd(&g_counts[i1], 1);
        atomicAdd(&g_hist[i0*NB + (int)(__float_as_uint(gg0) >> 17)], 1);
        atomicAdd(&g_hist[i1*NB + (int)(__float_as_uint(gg1) >> 17)], 1);
    }
    __syncthreads();
    if (tid < NE) atomicAdd(&g_imp[tid], s_imp[tid]);
    if (tid == 0) atomicAdd(&g_ent, s_ent);

    {
        const float4* src = (const float4*)(ctx + (size_t)blockIdx.x * 64 * DIMV);
        uint2* dst = (uint2*)(g_ctx_h + (size_t)blockIdx.x * 64 * DIMV);
#pragma unroll
        for (int i = 0; i < 16; i++) {
            int j = tid + i*256;
            float4 v = src[j];
            uint2 pk;
            pk.x = packh(__float2half_rn(v.x), __float2half_rn(v.y));
            pk.y = packh(__float2half_rn(v.z), __float2half_rn(v.w));
            dst[j] = pk;
        }
    }
}

// ---------------- capacity cutoff --------------------------------------------
__global__ void k_cutoff() {
    int e = blockIdx.x, tid = threadIdx.x;
    __shared__ int chunk[256], suffix[256];
    if (g_counts[e] <= CAP) {
        if (tid == 0) { g_bstar[e] = -1; g_rrem[e] = 0; }
        return;
    }
    const int* h = g_hist + e*NB;
    int b0 = tid * 128;
    int s = 0;
    for (int b = b0; b < b0 + 128; b++) s += h[b];
    chunk[tid] = s;
    __syncthreads();
    if (tid == 0) {
        int run = 0;
        for (int i = 255; i >= 0; i--) { suffix[i] = run; run += chunk[i]; }
    }
    __syncthreads();
    int cum = suffix[tid];
    for (int b = b0 + 127; b >= b0; b--) {
        int hb = h[b];
        if (cum < CAP && cum + hb >= CAP) {
            g_bstar[e] = b; g_rrem[e] = CAP - cum;
        }
        cum += hb;
    }
}

__global__ void k_flags() {
    int s = blockIdx.x * blockDim.x + threadIdx.x;
    if (s >= NSLOT) return;
    int e = g_expert[s];
    unsigned char kept;
    if (g_counts[e] <= CAP) kept = 1;
    else {
        int b  = (int)(__float_as_uint(g_gate[s]) >> 17);
        int bs = g_bstar[e];
        if (b > bs) kept = 1;
        else if (b < bs) kept = 0;
        else {
            kept = 0;
            int p = atomicAdd(&g_btotal, 1);
            g_blist[p] = s;
        }
    }
    g_kept[s] = kept;
}

__global__ void k_boundary() {
    int total = g_btotal;
    for (int i = blockIdx.x * blockDim.x + threadIdx.x; i < total;
         i += gridDim.x * blockDim.x) {
        int si = g_blist[i];
        int e  = g_expert[si];
        unsigned int ki = __float_as_uint(g_gate[si]);
        int better = 0;
        for (int j = 0; j < total; j++) {
            int sj = g_blist[j];
            if (g_expert[sj] != e) continue;
            unsigned int kj = __float_as_uint(g_gate[sj]);
            better += (kj > ki) || (kj == ki && sj < si);
        }
        if (better < g_rrem[e]) g_kept[si] = 1;
    }
}

__global__ void k_compact() {
    __shared__ int scnt[NE], sbase[NE];
    int tid = threadIdx.x;
    int s = blockIdx.x * 256 + tid;
    if (tid < NE) scnt[tid] = 0;
    __syncthreads();
    int e = -1, rank = 0;
    if (s < NSLOT && g_kept[s]) {
        e = g_expert[s];
        rank = atomicAdd(&scnt[e], 1);
    }
    __syncthreads();
    if (tid < NE && scnt[tid] > 0) sbase[tid] = atomicAdd(&g_cursor[tid], scnt[tid]);
    __syncthreads();
    if (e >= 0) g_perm[e*CAP + sbase[e] + rank] = s;
}

// ---------------- fused MLP, pipelined ---------------------------------------
__global__ void __launch_bounds__(256, 1)
k_mlp(const float* __restrict__ b1, const float* __restrict__ b2) {
    int e = blockIdx.z;
    int Me = min(g_counts[e], CAP);
    int m0 = blockIdx.x * 128;
    if (m0 >= Me) return;

    extern __shared__ __align__(16) char smem[];
    uint32_t sb = smem_u32(smem);
    int tid = threadIdx.x;
    int* sslot = (int*)smem;
    float* sgate = (float*)(smem + FS_GATE);
    if (tid < 128) {
        int gr = m0 + tid;
        if (gr < Me) {
            int s = g_perm[e*CAP + gr];
            sslot[tid] = s; sgate[tid] = g_gate[s];
        } else { sslot[tid] = -1; sgate[tid] = 0.f; }
    }
    __syncthreads();

    const __half* W1 = g_w1t + (size_t)e * HID * DIMV;
    const __half* W2 = g_w2t + (size_t)e * DIMV * HID;

#pragma unroll
    for (int i = 0; i < 16; i++) {
        int j = tid + i*256;
        int c = j >> 9, rem = j & 511;
        int row = rem >> 2, seg = rem & 3;
        int tok = sslot[row] >> 1;
        cpasync16(sb + FS_X + c*8192 + row*64 + ((seg ^ ((row>>1)&3))*16),
                  g_ctx_h + (size_t)max(tok, 0)*DIMV + c*32 + seg*8,
                  tok >= 0 ? 16 : 0);
    }
    CP_COMMIT();

    auto fill_w1 = [&](int st, int h0) {
#pragma unroll
        for (int i = 0; i < 8; i++) {
            int j = tid + i*256;
            int c = j >> 8, rem = j & 255;
            int r = rem >> 2, seg = rem & 3;
            cpasync16(sb + FS_W1 + st*32768 + c*4096 + r*64 + ((seg ^ ((r>>1)&3))*16),
                      W1 + (size_t)(h0 + r)*DIMV + c*32 + seg*8, 16);
        }
        CP_COMMIT();
    };
    auto fill_w2 = [&](int st, int h0) {
#pragma unroll
        for (int i = 0; i < 8; i++) {
            int j = tid + i*256;
            int kc = j >> 10, rem = j & 1023;
            int r = rem >> 2, seg = rem & 3;
            cpasync16(sb + FS_W2 + st*32768 + kc*16384 + r*64 + ((seg ^ ((r>>1)&3))*16),
                      W2 + (size_t)r*HID + h0 + kc*32 + seg*8, 16);
        }
        CP_COMMIT();
    };

    fill_w1(0, 0);
    fill_w2(0, 0);
    fill_w1(1, 64);

    int warp = tid >> 5, lane = tid & 31;
    int g = lane >> 2, tg = lane & 3;
    int wmP = (warp & 3) * 32, wnP = (warp >> 2) * 32;
    int wm = (warp & 1) * 64, wn = (warp >> 1) * 64;

    int lrA = lane & 15;
    int lrB = ((lane >> 4) & 1)*8 + (lane & 7);
    uint32_t x0 = (lane >> 1) & 1, x1 = (lane >> 2) & 1;
    uint32_t aSwz = ((((lane >> 4) & 1) ^ x0)) * 16;
    uint32_t bSwz = ((((lane >> 3) & 1) ^ x0)) * 16;
    uint32_t sx   = x1 * 32;
    uint32_t aP0 = (uint32_t)(wmP + lrA)*64 + aSwz;
    uint32_t bP0 = (uint32_t)(wnP + lrB)*64 + bSwz;
    uint32_t aO0 = (uint32_t)(wm + lrA)*64 + aSwz;
    uint32_t bO0 = (uint32_t)(wn + lrB)*64 + bSwz;
    uint32_t hsw = (uint32_t)((g >> 1) & 3);

    float accO[4][8][4];
#pragma unroll
    for (int a = 0; a < 4; a++)
#pragma unroll
        for (int b = 0; b < 8; b++)
#pragma unroll
            for (int cc = 0; cc < 4; cc++) accO[a][b][cc] = 0.f;

    const float* bias1 = b1 + (size_t)e * HID;

    CP_WAIT2();
    __syncthreads();
    {
        float accP[2][4][4];
#pragma unroll
        for (int a = 0; a < 2; a++)
#pragma unroll
            for (int b = 0; b < 4; b++)
#pragma unroll
                for (int cc = 0; cc < 4; cc++) accP[a][b][cc] = 0.f;
        uint32_t w1b = sb + FS_W1;
#pragma unroll
        for (int c = 0; c < 8; c++) {
#pragma unroll
            for (int s = 0; s < 2; s++) {
                uint32_t sterm = ((uint32_t)(s*32)) ^ sx;
                uint32_t Af[2][4], Bf[4][2];
#pragma unroll
                for (int mf = 0; mf < 2; mf++)
                    ldsm4(Af[mf], sb + FS_X + c*8192 + aP0 + mf*(16*64) + sterm);
#pragma unroll
                for (int p = 0; p < 2; p++)
                    ldsm4(&Bf[2*p][0], w1b + c*4096 + bP0 + p*(16*64) + sterm);
#pragma unroll
                for (int mf = 0; mf < 2; mf++)
#pragma unroll
                    for (int nf = 0; nf < 4; nf++)
                        mma16816(accP[mf][nf], Af[mf], Bf[nf]);
            }
        }
#pragma unroll
        for (int nf = 0; nf < 4; nf++) {
            int cl = wnP + nf*8 + tg*2;
            float2 bb = *(const float2*)(bias1 + cl);
            int kc = cl >> 5, colb = (cl & 31)*2;
            uint32_t coff = (uint32_t)kc*8192 +
                            (uint32_t)(((uint32_t)(colb >> 4) ^ hsw))*16 + (colb & 15);
#pragma unroll
            for (int mf = 0; mf < 2; mf++)
#pragma unroll
                for (int hv = 0; hv < 2; hv++) {
                    int row = wmP + mf*16 + g + hv*8;
                    float v0 = fmaxf(accP[mf][nf][hv*2+0] + bb.x, 0.f);
                    float v1 = fmaxf(accP[mf][nf][hv*2+1] + bb.y, 0.f);
                    sts32(sb + FS_H + coff + (uint32_t)row*64,
                          packh(__float2half_rn(v0), __float2half_rn(v1)));
                }
        }
    }

    for (int h = 0; h < 8; h++) {
        __syncthreads();
        if (h < 7) fill_w2((h + 1) & 1, (h + 1) * 64);
        if (h < 6) fill_w1(h & 1, (h + 2) * 64);
        if (h < 6) CP_WAIT2();
        else if (h == 6) CP_WAIT1();
        else CP_WAIT0();
        __syncthreads();

        if (h < 7) {
            int hp = h + 1;
            float accP[2][4][4];
#pragma unroll
            for (int a = 0; a < 2; a++)
#pragma unroll
                for (int b = 0; b < 4; b++)
#pragma unroll
                    for (int cc = 0; cc < 4; cc++) accP[a][b][cc] = 0.f;
            uint32_t w1b = sb + FS_W1 + (hp & 1)*32768;
#pragma unroll
            for (int c = 0; c < 8; c++) {
#pragma unroll
                for (int s = 0; s < 2; s++) {
                    uint32_t sterm = ((uint32_t)(s*32)) ^ sx;
                    uint32_t Af[2][4], Bf[4][2];
#pragma unroll
                    for (int mf = 0; mf < 2; mf++)
                        ldsm4(Af[mf], sb + FS_X + c*8192 + aP0 + mf*(16*64) + sterm);
#pragma unroll
                    for (int p = 0; p < 2; p++)
                        ldsm4(&Bf[2*p][0], w1b + c*4096 + bP0 + p*(16*64) + sterm);
#pragma unroll
                    for (int mf = 0; mf < 2; mf++)
#pragma unroll
                        for (int nf = 0; nf < 4; nf++)
                            mma16816(accP[mf][nf], Af[mf], Bf[nf]);
                }
            }
            uint32_t hdst = sb + FS_H + (hp & 1)*16384;
#pragma unroll
            for (int nf = 0; nf < 4; nf++) {
                int cl = wnP + nf*8 + tg*2;
                float2 bb = *(const float2*)(bias1 + hp*64 + cl);
                int kc = cl >> 5, colb = (cl & 31)*2;
                uint32_t coff = (uint32_t)kc*8192 +
                                (uint32_t)(((uint32_t)(colb >> 4) ^ hsw))*16 + (colb & 15);
#pragma unroll
                for (int mf = 0; mf < 2; mf++)
#pragma unroll
                    for (int hv = 0; hv < 2; hv++) {
                        int row = wmP + mf*16 + g + hv*8;
                        float v0 = fmaxf(accP[mf][nf][hv*2+0] + bb.x, 0.f);
                        float v1 = fmaxf(accP[mf][nf][hv*2+1] + bb.y, 0.f);
                        sts32(hdst + coff + (uint32_t)row*64,
                              packh(__float2half_rn(v0), __float2half_rn(v1)));
                    }
            }
        }

        uint32_t hb  = sb + FS_H  + (h & 1)*16384;
        uint32_t w2b = sb + FS_W2 + (h & 1)*32768;
#pragma unroll
        for (int kc = 0; kc < 2; kc++) {
#pragma unroll
            for (int s = 0; s < 2; s++) {
                uint32_t sterm = ((uint32_t)(s*32)) ^ sx;
                uint32_t Af[4][4], Bf[8][2];
#pragma unroll
                for (int mf = 0; mf < 4; mf++)
                    ldsm4(Af[mf], hb + kc*8192 + aO0 + mf*(16*64) + sterm);
#pragma unroll
                for (int p = 0; p < 4; p++)
                    ldsm4(&Bf[2*p][0], w2b + kc*16384 + bO0 + p*(16*64) + sterm);
#pragma unroll
                for (int mf = 0; mf < 4; mf++)
#pragma unroll
                    for (int nf = 0; nf < 8; nf++)
                        mma16816(accO[mf][nf], Af[mf], Bf[nf]);
            }
        }
    }

    const float* bias2 = b2 + (size_t)e * DIMV;
#pragma unroll
    for (int mf = 0; mf < 4; mf++) {
#pragma unroll
        for (int hv = 0; hv < 2; hv++) {
            int r = wm + mf*16 + g + hv*8;
            int slot = sslot[r];
            if (slot < 0) continue;
            float gate = sgate[r];
            __half* yr = g_y + (size_t)slot * DIMV;
#pragma unroll
            for (int nf = 0; nf < 8; nf++) {
                int col = wn + nf*8 + tg*2;
                float2 bb = *(const float2*)(bias2 + col);
                float v0 = (accO[mf][nf][hv*2+0] + bb.x) * gate;
                float v1 = (accO[mf][nf][hv*2+1] + bb.y) * gate;
                *(uint32_t*)(yr + col) = packh(__float2half_rn(v0), __float2half_rn(v1));
            }
        }
    }
}

// ---------------- combine (fp16 y) + fused finalize ---------------------------
__global__ void k_combine(float* __restrict__ out, int out_size) {
    int idx = blockIdx.x * blockDim.x + threadIdx.x;
    if (idx < NTOK * 32) {
        int t = idx >> 5, f = idx & 31;
        float r[8];
#pragma unroll
        for (int i = 0; i < 8; i++) r[i] = 0.f;
        if (g_kept[2*t]) {
            uint4 a = *(const uint4*)(g_y + (size_t)(2*t)*DIMV + f*8);
            const uint32_t* w = (const uint32_t*)&a;
#pragma unroll
            for (int i = 0; i < 4; i++) {
                __half2 h2 = *(const __half2*)&w[i];
                float2 v = __half22float2(h2);
                r[2*i] += v.x; r[2*i+1] += v.y;
            }
        }
        if (g_kept[2*t + 1]) {
            uint4 a = *(const uint4*)(g_y + (size_t)(2*t+1)*DIMV + f*8);
            const uint32_t* w = (const uint32_t*)&a;
#pragma unroll
            for (int i = 0; i < 4; i++) {
                __half2 h2 = *(const __half2*)&w[i];
                float2 v = __half22float2(h2);
                r[2*i] += v.x; r[2*i+1] += v.y;
            }
        }
        float* o = out + (size_t)t*DIMV + f*8;
        *(float4*)o     = make_float4(r[0], r[1], r[2], r[3]);
        *(float4*)(o+4) = make_float4(r[4], r[5], r[6], r[7]);
    }
    if (blockIdx.x == 0 && threadIdx.x < 32) {
        int lane = threadIdx.x;
        int c = (lane < NE) ? min(g_counts[lane], CAP) : 0;
        int tot = c;
#pragma unroll
        for (int off = 16; off; off >>= 1) tot += __shfl_xor_sync(0xffffffffu, tot, off);
        float denom = fmaxf((float)tot, 1.f);
        float aux = 0.f;
        if (lane < NE)
            aux = (g_imp[lane] / (float)NTOK) * ((float)c / denom) * (float)NE;
#pragma unroll
        for (int off = 16; off; off >>= 1) aux += __shfl_xor_sync(0xffffffffu, aux, off);
        int base = NTOK * DIMV;
        if (lane == 0 && out_size > base)     out[base]     = aux;
        if (lane == 0 && out_size > base + 1) out[base + 1] = g_ent / (float)NTOK;
        if (lane < NE && out_size > base + 2 + lane) out[base + 2 + lane] = (float)c;
    }
}

// ---------------- launch -----------------------------------------------------
extern "C" void kernel_launch(void* const* d_in, const int* in_sizes, int n_in,
                              void* d_out, int out_size) {
    const float* ctx = (const float*)d_in[0];
    const float* Wg  = (const float*)d_in[1];
    const float* bg  = (const float*)d_in[2];
    const float* W1  = (const float*)d_in[3];
    const float* b1  = (const float*)d_in[4];
    const float* W2  = (const float*)d_in[5];
    const float* b2  = (const float*)d_in[6];
    float* out = (float*)d_out;

    static cudaStream_t s1;
    static cudaEvent_t evFork, evJoin;
    static bool init_done = false;
    if (!init_done) {
        cudaFuncSetAttribute(k_mlp, cudaFuncAttributeMaxDynamicSharedMemorySize, FS_SZ);
        cudaStreamCreateWithFlags(&s1, cudaStreamNonBlocking);
        cudaEventCreateWithFlags(&evFork, cudaEventDisableTiming);
        cudaEventCreateWithFlags(&evJoin, cudaEventDisableTiming);
        init_done = true;
    }

    // main: zero (router depends on it)
    k_zero<<<512, 256>>>();

    // fork: weight transposes run concurrently with router + dispatch chain
    cudaEventRecord(evFork, 0);
    cudaStreamWaitEvent(s1, evFork, 0);
    k_transpose<<<dim3(HID/32, DIMV/32, NE), 256, 0, s1>>>(W1, 0, DIMV, HID);
    k_transpose<<<dim3(DIMV/32, HID/32, NE), 256, 0, s1>>>(W2, 1, HID, DIMV);
    cudaEventRecord(evJoin, s1);

    // main: router + dispatch
    k_router<<<NTOK/64, 256>>>(ctx, Wg, bg);
    k_cutoff<<<NE, 256>>>();
    k_flags<<<NSLOT/256, 256>>>();
    k_boundary<<<64, 256>>>();
    k_compact<<<(NSLOT + 255)/256, 256>>>();

    // join before MLP (needs transposed weights)
    cudaStreamWaitEvent(0, evJoin, 0);

    dim3 gm(MTILES, 1, NE);
    k_mlp<<<gm, 256, FS_SZ>>>(b1, b2);

    k_combine<<<(NTOK*32 + 255)/256, 256>>>(out, out_size);
}